// round 6
// baseline (speedup 1.0000x reference)
#include <cuda_runtime.h>
#include <cuda_bf16.h>

// KL divergence between diagonal Gaussians, reduced to a single flat sum:
//   S = sum over all B*N elements of:
//         log(s2/s1) + (s1 + (mask*(mu2-mu1))^2) / s2
//   out = 0.5 * S / B - n/2        (n = 256, B = 65536)
//
// Single-kernel: grid-stride partial sums + last-block-done final reduction.
// Memory-bound: 5 fp32 arrays of 64MB each = 320MB read, scalar float out.

#define TOT_ELEMS (65536LL * 256LL)
#define TOT4      (TOT_ELEMS / 4)          // 4,194,304 float4 groups
#define NBLK      1184                     // 8 * 148 SMs
#define NTHR      256

__device__ double       g_partials[NBLK];
__device__ unsigned int g_ticket = 0;      // reset to 0 by last block each call

__device__ __forceinline__ float kld_group(const float4 a, const float4 b,
                                           const float4 p, const float4 q,
                                           const float4 m)
{
    // nan_to_num on mu1
    float a0 = (a.x == a.x) ? a.x : 0.0f;
    float a1 = (a.y == a.y) ? a.y : 0.0f;
    float a2 = (a.z == a.z) ? a.z : 0.0f;
    float a3 = (a.w == a.w) ? a.w : 0.0f;

    float d0 = m.x * (b.x - a0);
    float d1 = m.y * (b.y - a1);
    float d2 = m.z * (b.z - a2);
    float d3 = m.w * (b.w - a3);

    float f0 = __logf(__fdividef(q.x, p.x)) + __fdividef(p.x + d0 * d0, q.x);
    float f1 = __logf(__fdividef(q.y, p.y)) + __fdividef(p.y + d1 * d1, q.y);
    float f2 = __logf(__fdividef(q.z, p.z)) + __fdividef(p.z + d2 * d2, q.z);
    float f3 = __logf(__fdividef(q.w, p.w)) + __fdividef(p.w + d3 * d3, q.w);

    return (f0 + f1) + (f2 + f3);
}

__global__ __launch_bounds__(NTHR)
void kld_kernel(const float4* __restrict__ mu1,
                const float4* __restrict__ mu2,
                const float4* __restrict__ s1,
                const float4* __restrict__ s2,
                const float4* __restrict__ mask,
                float* __restrict__ out)
{
    const long long stride = (long long)NBLK * NTHR;
    long long i = (long long)blockIdx.x * NTHR + threadIdx.x;

    double acc = 0.0;

    // Unroll x2: front-batch 10 LDG.128 per iteration for higher MLP.
    for (; i + stride < TOT4; i += 2 * stride) {
        const long long j = i + stride;
        float4 a0 = mu1[i];  float4 a1 = mu1[j];
        float4 b0 = mu2[i];  float4 b1 = mu2[j];
        float4 p0 = s1[i];   float4 p1 = s1[j];
        float4 q0 = s2[i];   float4 q1 = s2[j];
        float4 m0 = mask[i]; float4 m1 = mask[j];

        float g0 = kld_group(a0, b0, p0, q0, m0);
        float g1 = kld_group(a1, b1, p1, q1, m1);
        acc += (double)(g0 + g1);
    }
    if (i < TOT4) {
        acc += (double)kld_group(mu1[i], mu2[i], s1[i], s2[i], mask[i]);
    }

    // Warp reduce (double)
    #pragma unroll
    for (int off = 16; off > 0; off >>= 1)
        acc += __shfl_down_sync(0xFFFFFFFFu, acc, off);

    __shared__ double warp_sums[NTHR / 32];
    __shared__ bool   s_is_last;
    int lane = threadIdx.x & 31;
    int wid  = threadIdx.x >> 5;
    if (lane == 0) warp_sums[wid] = acc;
    __syncthreads();

    if (wid == 0) {
        double v = (lane < NTHR / 32) ? warp_sums[lane] : 0.0;
        #pragma unroll
        for (int off = 4; off > 0; off >>= 1)
            v += __shfl_down_sync(0xFFFFFFFFu, v, off);
        if (lane == 0) {
            g_partials[blockIdx.x] = v;
            __threadfence();
            unsigned int t = atomicAdd(&g_ticket, 1u);
            s_is_last = (t == NBLK - 1);
        }
    }
    __syncthreads();

    if (s_is_last) {
        // Last block: sum all partials and write the scalar result.
        double facc = 0.0;
        for (int k = threadIdx.x; k < NBLK; k += NTHR)
            facc += g_partials[k];

        #pragma unroll
        for (int off = 16; off > 0; off >>= 1)
            facc += __shfl_down_sync(0xFFFFFFFFu, facc, off);

        if (lane == 0) warp_sums[wid] = facc;
        __syncthreads();

        if (wid == 0) {
            double v = (lane < NTHR / 32) ? warp_sums[lane] : 0.0;
            #pragma unroll
            for (int off = 4; off > 0; off >>= 1)
                v += __shfl_down_sync(0xFFFFFFFFu, v, off);
            if (lane == 0) {
                out[0] = (float)(0.5 * v / 65536.0 - 128.0);
                g_ticket = 0;   // reset for next graph replay
            }
        }
    }
}

extern "C" void kernel_launch(void* const* d_in, const int* in_sizes, int n_in,
                              void* d_out, int out_size)
{
    const float4* mu1  = (const float4*)d_in[0];
    const float4* mu2  = (const float4*)d_in[1];
    const float4* s1   = (const float4*)d_in[2];
    const float4* s2   = (const float4*)d_in[3];
    const float4* mask = (const float4*)d_in[4];

    kld_kernel<<<NBLK, NTHR>>>(mu1, mu2, s1, s2, mask, (float*)d_out);
}

// round 7
// speedup vs baseline: 1.0982x; 1.0982x over previous
#include <cuda_runtime.h>
#include <cuda_bf16.h>

// KL divergence between diagonal Gaussians, reduced to a single flat sum:
//   S = sum over all B*N elements of:
//         log(s2/s1) + (s1 + (mask*(mu2-mu1))^2) / s2
//   out = 0.5 * S / B - n/2        (n = 256, B = 65536)
//
// Single-kernel: simple grid-stride partial sums (R4-proven loop) +
// last-block-done final reduction. 320MB read, scalar float out.

#define TOT4  4194304       // (65536*256)/4 float4 groups
#define NBLK  1184          // 8 * 148 SMs
#define NTHR  256

__device__ double       g_partials[NBLK];
__device__ unsigned int g_ticket = 0;      // reset to 0 by last block each call

__global__ __launch_bounds__(NTHR)
void kld_kernel(const float4* __restrict__ mu1,
                const float4* __restrict__ mu2,
                const float4* __restrict__ s1,
                const float4* __restrict__ s2,
                const float4* __restrict__ mask,
                float* __restrict__ out)
{
    const unsigned stride = NBLK * NTHR;
    unsigned i = blockIdx.x * NTHR + threadIdx.x;

    double acc = 0.0;

    for (; i < TOT4; i += stride) {
        float4 a = mu1[i];
        float4 b = mu2[i];
        float4 p = s1[i];
        float4 q = s2[i];
        float4 m = mask[i];

        // nan_to_num on mu1
        float a0 = (a.x == a.x) ? a.x : 0.0f;
        float a1 = (a.y == a.y) ? a.y : 0.0f;
        float a2 = (a.z == a.z) ? a.z : 0.0f;
        float a3 = (a.w == a.w) ? a.w : 0.0f;

        float d0 = m.x * (b.x - a0);
        float d1 = m.y * (b.y - a1);
        float d2 = m.z * (b.z - a2);
        float d3 = m.w * (b.w - a3);

        float f0 = __logf(__fdividef(q.x, p.x)) + __fdividef(p.x + d0 * d0, q.x);
        float f1 = __logf(__fdividef(q.y, p.y)) + __fdividef(p.y + d1 * d1, q.y);
        float f2 = __logf(__fdividef(q.z, p.z)) + __fdividef(p.z + d2 * d2, q.z);
        float f3 = __logf(__fdividef(q.w, p.w)) + __fdividef(p.w + d3 * d3, q.w);

        acc += (double)((f0 + f1) + (f2 + f3));
    }

    // Warp reduce (double)
    #pragma unroll
    for (int off = 16; off > 0; off >>= 1)
        acc += __shfl_down_sync(0xFFFFFFFFu, acc, off);

    __shared__ double warp_sums[NTHR / 32];
    __shared__ bool   s_is_last;
    int lane = threadIdx.x & 31;
    int wid  = threadIdx.x >> 5;
    if (lane == 0) warp_sums[wid] = acc;
    __syncthreads();

    if (wid == 0) {
        double v = (lane < NTHR / 32) ? warp_sums[lane] : 0.0;
        #pragma unroll
        for (int off = 4; off > 0; off >>= 1)
            v += __shfl_down_sync(0xFFFFFFFFu, v, off);
        if (lane == 0) {
            g_partials[blockIdx.x] = v;
            __threadfence();
            unsigned int t = atomicAdd(&g_ticket, 1u);
            s_is_last = (t == NBLK - 1);
        }
    }
    __syncthreads();

    if (s_is_last) {
        // Last block: sum all 1184 partials (L2-hot) and write the scalar.
        double facc = 0.0;
        for (int k = threadIdx.x; k < NBLK; k += NTHR)
            facc += g_partials[k];

        #pragma unroll
        for (int off = 16; off > 0; off >>= 1)
            facc += __shfl_down_sync(0xFFFFFFFFu, facc, off);

        if (lane == 0) warp_sums[wid] = facc;
        __syncthreads();

        if (wid == 0) {
            double v = (lane < NTHR / 32) ? warp_sums[lane] : 0.0;
            #pragma unroll
            for (int off = 4; off > 0; off >>= 1)
                v += __shfl_down_sync(0xFFFFFFFFu, v, off);
            if (lane == 0) {
                out[0] = (float)(0.5 * v / 65536.0 - 128.0);
                g_ticket = 0;   // reset for next graph replay
            }
        }
    }
}

extern "C" void kernel_launch(void* const* d_in, const int* in_sizes, int n_in,
                              void* d_out, int out_size)
{
    const float4* mu1  = (const float4*)d_in[0];
    const float4* mu2  = (const float4*)d_in[1];
    const float4* s1   = (const float4*)d_in[2];
    const float4* s2   = (const float4*)d_in[3];
    const float4* mask = (const float4*)d_in[4];

    kld_kernel<<<NBLK, NTHR>>>(mu1, mu2, s1, s2, mask, (float*)d_out);
}

// round 8
// speedup vs baseline: 1.1026x; 1.0040x over previous
#include <cuda_runtime.h>
#include <cuda_bf16.h>

// KL divergence between diagonal Gaussians, reduced to a single flat sum:
//   S = sum over all B*N elements of:
//         log(s2/s1) + (s1 + (mask*(mu2-mu1))^2) / s2
//   out = 0.5 * S / B - n/2        (n = 256, B = 65536)
//
// Single-kernel: simple grid-stride partial sums + last-block-done final
// reduction. 320MB read (streaming, evict-first), scalar float out.

#define TOT4  4194304       // (65536*256)/4 float4 groups
#define NBLK  1184          // 8 * 148 SMs
#define NTHR  256

__device__ double       g_partials[NBLK];
__device__ unsigned int g_ticket = 0;      // reset to 0 by last block each call

__global__ __launch_bounds__(NTHR)
void kld_kernel(const float4* __restrict__ mu1,
                const float4* __restrict__ mu2,
                const float4* __restrict__ s1,
                const float4* __restrict__ s2,
                const float4* __restrict__ mask,
                float* __restrict__ out)
{
    const unsigned stride = NBLK * NTHR;
    unsigned i = blockIdx.x * NTHR + threadIdx.x;

    double acc = 0.0;

    for (; i < TOT4; i += stride) {
        // Streaming (evict-first) loads: no reuse anywhere, keep L2 clean.
        float4 a = __ldcs(&mu1[i]);
        float4 b = __ldcs(&mu2[i]);
        float4 p = __ldcs(&s1[i]);
        float4 q = __ldcs(&s2[i]);
        float4 m = __ldcs(&mask[i]);

        // nan_to_num on mu1
        float a0 = (a.x == a.x) ? a.x : 0.0f;
        float a1 = (a.y == a.y) ? a.y : 0.0f;
        float a2 = (a.z == a.z) ? a.z : 0.0f;
        float a3 = (a.w == a.w) ? a.w : 0.0f;

        float d0 = m.x * (b.x - a0);
        float d1 = m.y * (b.y - a1);
        float d2 = m.z * (b.z - a2);
        float d3 = m.w * (b.w - a3);

        float f0 = __logf(__fdividef(q.x, p.x)) + __fdividef(p.x + d0 * d0, q.x);
        float f1 = __logf(__fdividef(q.y, p.y)) + __fdividef(p.y + d1 * d1, q.y);
        float f2 = __logf(__fdividef(q.z, p.z)) + __fdividef(p.z + d2 * d2, q.z);
        float f3 = __logf(__fdividef(q.w, p.w)) + __fdividef(p.w + d3 * d3, q.w);

        acc += (double)((f0 + f1) + (f2 + f3));
    }

    // Warp reduce (double)
    #pragma unroll
    for (int off = 16; off > 0; off >>= 1)
        acc += __shfl_down_sync(0xFFFFFFFFu, acc, off);

    __shared__ double warp_sums[NTHR / 32];
    __shared__ bool   s_is_last;
    int lane = threadIdx.x & 31;
    int wid  = threadIdx.x >> 5;
    if (lane == 0) warp_sums[wid] = acc;
    __syncthreads();

    if (wid == 0) {
        double v = (lane < NTHR / 32) ? warp_sums[lane] : 0.0;
        #pragma unroll
        for (int off = 4; off > 0; off >>= 1)
            v += __shfl_down_sync(0xFFFFFFFFu, v, off);
        if (lane == 0) {
            g_partials[blockIdx.x] = v;
            __threadfence();
            unsigned int t = atomicAdd(&g_ticket, 1u);
            s_is_last = (t == NBLK - 1);
        }
    }
    __syncthreads();

    if (s_is_last) {
        // Last block: sum all 1184 partials (L2-hot) and write the scalar.
        double facc = 0.0;
        for (int k = threadIdx.x; k < NBLK; k += NTHR)
            facc += g_partials[k];

        #pragma unroll
        for (int off = 16; off > 0; off >>= 1)
            facc += __shfl_down_sync(0xFFFFFFFFu, facc, off);

        if (lane == 0) warp_sums[wid] = facc;
        __syncthreads();

        if (wid == 0) {
            double v = (lane < NTHR / 32) ? warp_sums[lane] : 0.0;
            #pragma unroll
            for (int off = 4; off > 0; off >>= 1)
                v += __shfl_down_sync(0xFFFFFFFFu, v, off);
            if (lane == 0) {
                out[0] = (float)(0.5 * v / 65536.0 - 128.0);
                g_ticket = 0;   // reset for next graph replay
            }
        }
    }
}

extern "C" void kernel_launch(void* const* d_in, const int* in_sizes, int n_in,
                              void* d_out, int out_size)
{
    const float4* mu1  = (const float4*)d_in[0];
    const float4* mu2  = (const float4*)d_in[1];
    const float4* s1   = (const float4*)d_in[2];
    const float4* s2   = (const float4*)d_in[3];
    const float4* mask = (const float4*)d_in[4];

    kld_kernel<<<NBLK, NTHR>>>(mu1, mu2, s1, s2, mask, (float*)d_out);
}